// round 14
// baseline (speedup 1.0000x reference)
#include <cuda_runtime.h>
#include <cuda_bf16.h>

// ---------------------------------------------------------------------------
// Multi-scale region distillation loss — single fused kernel.
// 256-thread blocks; channel split is INTRA-WARP (half-warps own half the
// channels, combined via shfl_xor) so warps are fully autonomous: no smem
// partial exchange, no extra barriers. Register-batched loads (16 LDG.64
// in flight per thread).
// Scales: (128,128) (64,64) (32,32) (16,16), B=8, C=256, labels 512x512 int32.
// loss = sum_s w_s * sum_k present_k * factor_k * (1 - mean_k(cos_sim))
//
// Last-block-done pattern: scratch is zero at module load; the final block
// computes the loss AND resets scratch+counter to zero, so every CUDA-graph
// replay starts from a clean state. One launch total.
// ---------------------------------------------------------------------------

#define NC 21          // num_class (labels guarded against out-of-range anyway)
#define CCH 256        // channels
#define NBLK 680       // total blocks (see ranges below)
#define NTHR 256       // 8 warps x 32 pixels each = 256 px/block

__device__ float g_sum[4][NC];          // zero-initialized at load
__device__ float g_cnt[4][NC];
__device__ unsigned int g_done = 0;

// Each warp handles 32 pixels: lanes 0-15 reduce channels [0,128) for pixel
// pairs 0..15, lanes 16-31 reduce channels [128,256) for the same pairs.
// Halves combine via shfl_xor(16); lanes 0-15 finish (cosine+label+atomics).
template <int H, int W>
__device__ __forceinline__ void scale_body(
    int blk, int warp, int lane,
    const float* __restrict__ f,
    const float* __restrict__ fo,
    const int* __restrict__ lab,
    float* s_sum, float* s_cnt)
{
    constexpr int HW = H * W;
    constexpr int DS = 512 / H;            // nearest-neighbor stride (exact)

    const int half = lane >> 4;            // 0 or 1: channel half
    const int p    = lane & 15;            // pixel-pair slot within warp

    const int g0  = blk * 256 + warp * 32 + 2 * p;   // global pixel index (even)
    const int b   = g0 / HW;                          // compile-time pow2 div
    const int rem = g0 - b * HW;                      // pixel within image
    const int h   = rem / W;
    const int w   = rem - h * W;                      // even, so w+1 < W

    const float* __restrict__ fp  = f  + (size_t)b * CCH * HW + (size_t)half * (CCH / 2) * HW + rem;
    const float* __restrict__ fop = fo + (size_t)b * CCH * HW + (size_t)half * (CCH / 2) * HW + rem;

    float d0 = 0.f, d1 = 0.f;      // dot(f, fo)
    float a0 = 0.f, a1 = 0.f;      // |f|^2
    float c0 = 0.f, c1 = 0.f;      // |fo|^2

    // Front-batch 16 LDG.64 per iteration so the loads overlap
    // (needs the 51-reg budget from __launch_bounds__(256, 5)).
    for (int c = 0; c < CCH / 2; c += 8) {
        float2 x[8], y[8];
#pragma unroll
        for (int j = 0; j < 8; j++) {
            x[j] = *reinterpret_cast<const float2*>(fp  + (size_t)(c + j) * HW);
            y[j] = *reinterpret_cast<const float2*>(fop + (size_t)(c + j) * HW);
        }
#pragma unroll
        for (int j = 0; j < 8; j++) {
            d0 = fmaf(x[j].x, y[j].x, d0);  d1 = fmaf(x[j].y, y[j].y, d1);
            a0 = fmaf(x[j].x, x[j].x, a0);  a1 = fmaf(x[j].y, x[j].y, a1);
            c0 = fmaf(y[j].x, y[j].x, c0);  c1 = fmaf(y[j].y, y[j].y, c1);
        }
    }

    // combine channel halves within the warp — no smem, no barrier
    d0 += __shfl_xor_sync(0xffffffffu, d0, 16);
    d1 += __shfl_xor_sync(0xffffffffu, d1, 16);
    a0 += __shfl_xor_sync(0xffffffffu, a0, 16);
    a1 += __shfl_xor_sync(0xffffffffu, a1, 16);
    c0 += __shfl_xor_sync(0xffffffffu, c0, 16);
    c1 += __shfl_xor_sync(0xffffffffu, c1, 16);

    if (half == 0) {
        const float EPS = 1e-8f;
        float sim0 = d0 / (fmaxf(sqrtf(a0), EPS) * fmaxf(sqrtf(c0), EPS));
        float sim1 = d1 / (fmaxf(sqrtf(a1), EPS) * fmaxf(sqrtf(c1), EPS));

        // nearest-downsampled label lookup (labels are 512x512 per image)
        const int lbase = b * (512 * 512) + (h * DS) * 512;
        int l0 = lab[lbase + w * DS];
        int l1 = lab[lbase + (w + 1) * DS];

        if ((unsigned)l0 < NC) { atomicAdd(&s_sum[l0], sim0); atomicAdd(&s_cnt[l0], 1.0f); }
        if ((unsigned)l1 < NC) { atomicAdd(&s_sum[l1], sim1); atomicAdd(&s_cnt[l1], 1.0f); }
    }
}

// Block ranges (256 pixels/block):
//   scale0: 8*128*128/256 = 512 blocks   [0,   512)
//   scale1: 8*64*64/256   = 128 blocks   [512, 640)
//   scale2: 8*32*32/256   = 32  blocks   [640, 672)
//   scale3: 8*16*16/256   = 8   blocks   [672, 680)
__global__ void __launch_bounds__(NTHR, 5) msrd_fused_kernel(
    const int*   __restrict__ lab,
    const float* __restrict__ f0,  const float* __restrict__ f1,
    const float* __restrict__ f2,  const float* __restrict__ f3,
    const float* __restrict__ fo0, const float* __restrict__ fo1,
    const float* __restrict__ fo2, const float* __restrict__ fo3,
    const int*   __restrict__ nc_p,
    const int*   __restrict__ noc_p,
    float*       __restrict__ out)
{
    __shared__ float s_sum[NC];
    __shared__ float s_cnt[NC];
    __shared__ float s_red[NTHR];
    __shared__ int   s_last;

    const int tid  = threadIdx.x;
    const int warp = tid >> 5;
    const int lane = tid & 31;

    if (tid < NC) { s_sum[tid] = 0.f; s_cnt[tid] = 0.f; }
    __syncthreads();

    const int blk = blockIdx.x;
    int sid;
    if (blk < 512)      { sid = 0; scale_body<128, 128>(blk,       warp, lane, f0, fo0, lab, s_sum, s_cnt); }
    else if (blk < 640) { sid = 1; scale_body< 64,  64>(blk - 512, warp, lane, f1, fo1, lab, s_sum, s_cnt); }
    else if (blk < 672) { sid = 2; scale_body< 32,  32>(blk - 640, warp, lane, f2, fo2, lab, s_sum, s_cnt); }
    else                { sid = 3; scale_body< 16,  16>(blk - 672, warp, lane, f3, fo3, lab, s_sum, s_cnt); }

    __syncthreads();
    if (tid < NC) {
        atomicAdd(&g_sum[sid][tid], s_sum[tid]);
        atomicAdd(&g_cnt[sid][tid], s_cnt[tid]);
    }

    // ---- release our contributions, count arrivals ----
    __threadfence();
    __syncthreads();
    if (tid == 0) {
        unsigned int prev = atomicAdd(&g_done, 1u);
        s_last = (prev == (unsigned int)(gridDim.x - 1)) ? 1 : 0;
    }
    __syncthreads();
    if (!s_last) return;

    // ---- last block: parallel finalize ----
    __threadfence();                       // acquire side
    const int ncls = nc_p ? nc_p[0] : NC;
    const int nold = noc_p ? noc_p[0] : 15;

    float term = 0.f;
    int s = tid / NC;                      // 0..3 for tid < 84
    int k = tid - s * NC;
    if (tid < 4 * NC) {
        float cnt = __ldcg(&g_cnt[s][k]);
        float sum = __ldcg(&g_sum[s][k]);
        if (cnt > 0.f && k < ncls) {
            float mean = sum / fmaxf(cnt, 1.0f);
            float factor;
            if (k == 0)          factor = (float)nold / (float)ncls;
            else if (k <= nold)  factor = 1.0f;
            else                 factor = 0.0f;
            term = (float)(s + 1) * factor * (1.0f - mean);
        }
    }
    s_red[tid] = term;
    __syncthreads();
#pragma unroll
    for (int off = NTHR / 2; off > 0; off >>= 1) {
        if (tid < off) s_red[tid] += s_red[tid + off];
        __syncthreads();
    }
    if (tid == 0) out[0] = s_red[0];

    // ---- reset scratch for the next graph replay ----
    if (tid < 4 * NC) {
        g_sum[s][k] = 0.0f;
        g_cnt[s][k] = 0.0f;
    }
    if (tid == 0) g_done = 0u;
}

extern "C" void kernel_launch(void* const* d_in, const int* in_sizes, int n_in,
                              void* d_out, int out_size)
{
    (void)out_size;

    // --- robust input matching by element count ----------------------------
    // setup_inputs() dict order: pseudo_labels, f0, fo0, f1, fo1, f2, fo2,
    // f3, fo3, num_class, num_old_class. Labels pinned at index 0; each
    // feature size appears exactly twice with f preceding fo; size-1 entries
    // are num_class then num_old_class.
    const long long SZ0 = 8LL * 256 * 128 * 128;   // 33,554,432
    const long long SZ1 = 8LL * 256 *  64 *  64;   //  8,388,608
    const long long SZ2 = 8LL * 256 *  32 *  32;   //  2,097,152 (== labels size)
    const long long SZ3 = 8LL * 256 *  16 *  16;   //    524,288

    const int* lab = (const int*)d_in[0];          // labels always first input
    const float* f[4]  = {0, 0, 0, 0};
    const float* fo[4] = {0, 0, 0, 0};
    const int* ncp = 0;
    const int* nop = 0;

    for (int i = 1; i < n_in; i++) {
        long long n = (long long)in_sizes[i];
        int s = -1;
        if      (n == SZ0) s = 0;
        else if (n == SZ1) s = 1;
        else if (n == SZ2) s = 2;
        else if (n == SZ3) s = 3;
        else if (n == 1) {
            if (!ncp) ncp = (const int*)d_in[i];
            else if (!nop) nop = (const int*)d_in[i];
            continue;
        }
        if (s >= 0) {
            if (!f[s]) f[s] = (const float*)d_in[i];
            else if (!fo[s]) fo[s] = (const float*)d_in[i];
        }
    }

    msrd_fused_kernel<<<NBLK, NTHR>>>(lab, f[0], f[1], f[2], f[3],
                                           fo[0], fo[1], fo[2], fo[3],
                                           ncp, nop, (float*)d_out);
}

// round 15
// speedup vs baseline: 1.0322x; 1.0322x over previous
#include <cuda_runtime.h>
#include <cuda_bf16.h>

// ---------------------------------------------------------------------------
// Multi-scale region distillation loss — single fused kernel, 2-way channel
// split per block (smem combine — R12 config, best measured), register-
// batched loads (16 LDG.64 in flight per thread), streaming cache hints.
// Scales: (128,128) (64,64) (32,32) (16,16), B=8, C=256, labels 512x512 int32.
// loss = sum_s w_s * sum_k present_k * factor_k * (1 - mean_k(cos_sim))
//
// Last-block-done pattern: scratch is zero at module load; the final block
// computes the loss AND resets scratch+counter to zero, so every CUDA-graph
// replay starts from a clean state. One launch total.
// ---------------------------------------------------------------------------

#define NC 21          // num_class (labels guarded against out-of-range anyway)
#define CCH 256        // channels
#define NBLK 680       // total blocks (see ranges below)
#define NTHR 256       // 2 channel-halves x 128 threads

__device__ float g_sum[4][NC];          // zero-initialized at load
__device__ float g_cnt[4][NC];
__device__ unsigned int g_done = 0;

// Block handles 256 pixels. Threads [0,128) reduce channels [0,128),
// threads [128,256) reduce channels [128,256); halves combine via smem and
// half 0 finishes (cosine + label + class atomics).
template <int H, int W>
__device__ __forceinline__ void scale_body(
    int blk, int half, int wg_tid,
    const float* __restrict__ f,
    const float* __restrict__ fo,
    const int* __restrict__ lab,
    float* s_sum, float* s_cnt,
    float (*s_part)[128])              // [6][128] partials from half 1
{
    constexpr int HW = H * W;
    constexpr int DS = 512 / H;            // nearest-neighbor stride (exact)

    const int g0  = blk * 256 + 2 * wg_tid;          // global pixel index (even)
    const int b   = g0 / HW;                          // compile-time pow2 div
    const int rem = g0 - b * HW;                      // pixel within image
    const int h   = rem / W;
    const int w   = rem - h * W;                      // even, so w+1 < W

    const float* __restrict__ fp  = f  + (size_t)b * CCH * HW + (size_t)half * (CCH / 2) * HW + rem;
    const float* __restrict__ fop = fo + (size_t)b * CCH * HW + (size_t)half * (CCH / 2) * HW + rem;

    float d0 = 0.f, d1 = 0.f;      // dot(f, fo)
    float a0 = 0.f, a1 = 0.f;      // |f|^2
    float c0 = 0.f, c1 = 0.f;      // |fo|^2

    // Explicitly front-batch 16 LDG.64 per iteration so the loads overlap
    // (needs the 51-reg budget from __launch_bounds__(256, 5)).
    // __ldcs: features are read-once streaming data — evict-first so they
    // don't churn L2 (labels, reused 4x across scales, stay resident).
    for (int c = 0; c < CCH / 2; c += 8) {
        float2 x[8], y[8];
#pragma unroll
        for (int j = 0; j < 8; j++) {
            x[j] = __ldcs(reinterpret_cast<const float2*>(fp  + (size_t)(c + j) * HW));
            y[j] = __ldcs(reinterpret_cast<const float2*>(fop + (size_t)(c + j) * HW));
        }
#pragma unroll
        for (int j = 0; j < 8; j++) {
            d0 = fmaf(x[j].x, y[j].x, d0);  d1 = fmaf(x[j].y, y[j].y, d1);
            a0 = fmaf(x[j].x, x[j].x, a0);  a1 = fmaf(x[j].y, x[j].y, a1);
            c0 = fmaf(y[j].x, y[j].x, c0);  c1 = fmaf(y[j].y, y[j].y, c1);
        }
    }

    // combine halves: half 1 publishes, half 0 accumulates + finishes
    if (half == 1) {
        s_part[0][wg_tid] = d0;  s_part[1][wg_tid] = d1;
        s_part[2][wg_tid] = a0;  s_part[3][wg_tid] = a1;
        s_part[4][wg_tid] = c0;  s_part[5][wg_tid] = c1;
    }
    __syncthreads();
    if (half == 1) return;

    d0 += s_part[0][wg_tid];  d1 += s_part[1][wg_tid];
    a0 += s_part[2][wg_tid];  a1 += s_part[3][wg_tid];
    c0 += s_part[4][wg_tid];  c1 += s_part[5][wg_tid];

    const float EPS = 1e-8f;
    float sim0 = d0 / (fmaxf(sqrtf(a0), EPS) * fmaxf(sqrtf(c0), EPS));
    float sim1 = d1 / (fmaxf(sqrtf(a1), EPS) * fmaxf(sqrtf(c1), EPS));

    // nearest-downsampled label lookup (labels are 512x512 per image)
    const int lbase = b * (512 * 512) + (h * DS) * 512;
    int l0 = lab[lbase + w * DS];
    int l1 = lab[lbase + (w + 1) * DS];

    if ((unsigned)l0 < NC) { atomicAdd(&s_sum[l0], sim0); atomicAdd(&s_cnt[l0], 1.0f); }
    if ((unsigned)l1 < NC) { atomicAdd(&s_sum[l1], sim1); atomicAdd(&s_cnt[l1], 1.0f); }
}

// Block ranges (256 pixels/block):
//   scale0: 8*128*128/256 = 512 blocks   [0,   512)
//   scale1: 8*64*64/256   = 128 blocks   [512, 640)
//   scale2: 8*32*32/256   = 32  blocks   [640, 672)
//   scale3: 8*16*16/256   = 8   blocks   [672, 680)
__global__ void __launch_bounds__(NTHR, 5) msrd_fused_kernel(
    const int*   __restrict__ lab,
    const float* __restrict__ f0,  const float* __restrict__ f1,
    const float* __restrict__ f2,  const float* __restrict__ f3,
    const float* __restrict__ fo0, const float* __restrict__ fo1,
    const float* __restrict__ fo2, const float* __restrict__ fo3,
    const int*   __restrict__ nc_p,
    const int*   __restrict__ noc_p,
    float*       __restrict__ out)
{
    __shared__ float s_sum[NC];
    __shared__ float s_cnt[NC];
    __shared__ float s_part[6][128];
    __shared__ float s_red[NTHR];
    __shared__ int   s_last;

    const int tid    = threadIdx.x;
    const int half   = tid >> 7;           // 0 or 1
    const int wg_tid = tid & 127;

    if (tid < NC) { s_sum[tid] = 0.f; s_cnt[tid] = 0.f; }
    __syncthreads();

    const int blk = blockIdx.x;
    int sid;
    if (blk < 512)      { sid = 0; scale_body<128, 128>(blk,       half, wg_tid, f0, fo0, lab, s_sum, s_cnt, s_part); }
    else if (blk < 640) { sid = 1; scale_body< 64,  64>(blk - 512, half, wg_tid, f1, fo1, lab, s_sum, s_cnt, s_part); }
    else if (blk < 672) { sid = 2; scale_body< 32,  32>(blk - 640, half, wg_tid, f2, fo2, lab, s_sum, s_cnt, s_part); }
    else                { sid = 3; scale_body< 16,  16>(blk - 672, half, wg_tid, f3, fo3, lab, s_sum, s_cnt, s_part); }

    __syncthreads();
    if (tid < NC) {
        atomicAdd(&g_sum[sid][tid], s_sum[tid]);
        atomicAdd(&g_cnt[sid][tid], s_cnt[tid]);
    }

    // ---- release our contributions, count arrivals ----
    __threadfence();
    __syncthreads();
    if (tid == 0) {
        unsigned int prev = atomicAdd(&g_done, 1u);
        s_last = (prev == (unsigned int)(gridDim.x - 1)) ? 1 : 0;
    }
    __syncthreads();
    if (!s_last) return;

    // ---- last block: parallel finalize ----
    __threadfence();                       // acquire side
    const int ncls = nc_p ? nc_p[0] : NC;
    const int nold = noc_p ? noc_p[0] : 15;

    float term = 0.f;
    int s = tid / NC;                      // 0..3 for tid < 84
    int k = tid - s * NC;
    if (tid < 4 * NC) {
        float cnt = __ldcg(&g_cnt[s][k]);
        float sum = __ldcg(&g_sum[s][k]);
        if (cnt > 0.f && k < ncls) {
            float mean = sum / fmaxf(cnt, 1.0f);
            float factor;
            if (k == 0)          factor = (float)nold / (float)ncls;
            else if (k <= nold)  factor = 1.0f;
            else                 factor = 0.0f;
            term = (float)(s + 1) * factor * (1.0f - mean);
        }
    }
    s_red[tid] = term;
    __syncthreads();
#pragma unroll
    for (int off = NTHR / 2; off > 0; off >>= 1) {
        if (tid < off) s_red[tid] += s_red[tid + off];
        __syncthreads();
    }
    if (tid == 0) out[0] = s_red[0];

    // ---- reset scratch for the next graph replay ----
    if (tid < 4 * NC) {
        g_sum[s][k] = 0.0f;
        g_cnt[s][k] = 0.0f;
    }
    if (tid == 0) g_done = 0u;
}

extern "C" void kernel_launch(void* const* d_in, const int* in_sizes, int n_in,
                              void* d_out, int out_size)
{
    (void)out_size;

    // --- robust input matching by element count ----------------------------
    // setup_inputs() dict order: pseudo_labels, f0, fo0, f1, fo1, f2, fo2,
    // f3, fo3, num_class, num_old_class. Labels pinned at index 0; each
    // feature size appears exactly twice with f preceding fo; size-1 entries
    // are num_class then num_old_class.
    const long long SZ0 = 8LL * 256 * 128 * 128;   // 33,554,432
    const long long SZ1 = 8LL * 256 *  64 *  64;   //  8,388,608
    const long long SZ2 = 8LL * 256 *  32 *  32;   //  2,097,152 (== labels size)
    const long long SZ3 = 8LL * 256 *  16 *  16;   //    524,288

    const int* lab = (const int*)d_in[0];          // labels always first input
    const float* f[4]  = {0, 0, 0, 0};
    const float* fo[4] = {0, 0, 0, 0};
    const int* ncp = 0;
    const int* nop = 0;

    for (int i = 1; i < n_in; i++) {
        long long n = (long long)in_sizes[i];
        int s = -1;
        if      (n == SZ0) s = 0;
        else if (n == SZ1) s = 1;
        else if (n == SZ2) s = 2;
        else if (n == SZ3) s = 3;
        else if (n == 1) {
            if (!ncp) ncp = (const int*)d_in[i];
            else if (!nop) nop = (const int*)d_in[i];
            continue;
        }
        if (s >= 0) {
            if (!f[s]) f[s] = (const float*)d_in[i];
            else if (!fo[s]) fo[s] = (const float*)d_in[i];
        }
    }

    msrd_fused_kernel<<<NBLK, NTHR>>>(lab, f[0], f[1], f[2], f[3],
                                           fo[0], fo[1], fo[2], fo[3],
                                           ncp, nop, (float*)d_out);
}